// round 14
// baseline (speedup 1.0000x reference)
#include <cuda_runtime.h>
#include <math.h>

#define BB 8
#define MM 6
#define FF 97
#define TT 1200
#define GG 36

#define PI_F     3.14159274101257324f
#define TWOPI_F  6.28318548202514648f
#define DEN_THR  1e-2f

__device__ float4 g_wpack[FF * GG * MM];
__device__ float  g_svre[BB * MM * FF];

// ---------------------------------------------------------------------------
// f32x2 packed helpers (sm_10x)
// ---------------------------------------------------------------------------
__device__ __forceinline__ unsigned long long pk2(float lo, float hi) {
    unsigned long long r;
    asm("mov.b64 %0, {%1, %2};" : "=l"(r) : "f"(lo), "f"(hi));
    return r;
}
__device__ __forceinline__ void upk2(unsigned long long v, float& lo, float& hi) {
    asm("mov.b64 {%0, %1}, %2;" : "=f"(lo), "=f"(hi) : "l"(v));
}
__device__ __forceinline__ unsigned long long fma2(unsigned long long a,
                                                   unsigned long long b,
                                                   unsigned long long c) {
    unsigned long long d;
    asm("fma.rn.f32x2 %0, %1, %2, %3;" : "=l"(d) : "l"(a), "l"(b), "l"(c));
    return d;
}

// ---------------------------------------------------------------------------
__global__ void init_w_kernel() {
    int idx = blockIdx.x * blockDim.x + threadIdx.x;
    if (idx >= FF * GG * MM) return;
    int m = idx % MM;
    int g = (idx / MM) % GG;
    int f = idx / (MM * GG);

    double angm = 2.0 * M_PI * (double)m / 6.0;
    double lx = 0.05 * (cos(angm) - 1.0);
    double ly = 0.05 * sin(angm);
    double grid = (double)g * M_PI / 18.0;
    double dly = lx * cos(grid) + ly * sin(grid);
    double arg = -2.0 * M_PI * (double)f * dly;
    float wre = (float)(cos(arg) / 343.0);
    float wim = (float)(sin(arg) / 343.0);
    g_wpack[idx] = make_float4(wre, wre, -wim, wim);
}

// ---------------------------------------------------------------------------
// Re(sv): trig via double (matches CR f32 libm), arithmetic unfused f32.
// ---------------------------------------------------------------------------
__global__ void init_sv_kernel(const float* __restrict__ angle) {
    int idx = blockIdx.x * blockDim.x + threadIdx.x;
    if (idx >= BB * MM * FF) return;
    int f = idx % FF;
    int h = (idx / FF) % MM;
    int b = idx / (FF * MM);

    const int pa[6] = {0, 1, 2, 0, 2, 4};
    const int pb[6] = {3, 4, 5, 1, 3, 5};
    int ia = pa[h], ib = pb[h];
    double la_x = 0.05 * (cos(2.0 * M_PI * (double)ia / 6.0) - 1.0);
    double la_y = 0.05 * sin(2.0 * M_PI * (double)ia / 6.0);
    double lb_x = 0.05 * (cos(2.0 * M_PI * (double)ib / 6.0) - 1.0);
    double lb_y = 0.05 * sin(2.0 * M_PI * (double)ib / 6.0);
    float dxy0 = (float)(lb_x - la_x);
    float dxy1 = (float)(lb_y - la_y);

    float a  = angle[b];
    float ca = (float)cos((double)a);     // CR f32 cos
    float sa = (float)sin((double)a);     // CR f32 sin
    float delay = __fadd_rn(__fmul_rn(dxy0, ca), __fmul_rn(dxy1, sa));

    float freqf = (float)((double)f * 48000.0 / 97.0);
    float t1 = __fmul_rn(TWOPI_F, freqf);
    float t2 = __fmul_rn(t1, delay);
    float t3 = __fdiv_rn(t2, 343.0f);
    g_svre[idx] = (float)cos((double)t3); // CR f32 cos
}

// ---------------------------------------------------------------------------
// Main fused kernel, two-tier:
//  fast path: libdevice f32 trig everywhere (1-2 ulp), den_fast computed;
//  slow path (|den_fast| < DEN_THR, ~0.3% of samples): recompute the ipd/den
//  chain with double-rounded trig (bit-matching CR f32 libm), all surrounding
//  arithmetic unfused f32 == exact reference semantics.
// ---------------------------------------------------------------------------
__global__ void __launch_bounds__(256)
tasnet_fused_kernel(const float* __restrict__ mag,
                    const float* __restrict__ ph,
                    float* __restrict__ out) {
    __shared__ float4 sw[GG * MM];
    __shared__ float  ssv[MM];

    int bf = blockIdx.x;
    int f = bf % FF;
    int b = bf / FF;

    for (int i = threadIdx.x; i < GG * MM; i += blockDim.x)
        sw[i] = g_wpack[f * GG * MM + i];
    if (threadIdx.x < MM)
        ssv[threadIdx.x] = g_svre[(b * MM + threadIdx.x) * FF + f];
    __syncthreads();

    int t = blockIdx.y * blockDim.x + threadIdx.x;
    if (t >= TT) return;

    // ---- FAST: complex spectrogram via libdevice f32 trig ----
    const int base_in = (b * MM) * (FF * TT) + f * TT + t;
    float pphase[MM], pmag[MM];
    float re[MM], im[MM];
#pragma unroll
    for (int m = 0; m < MM; m++) {
        float mg = mag[base_in + m * (FF * TT)];
        float p  = ph [base_in + m * (FF * TT)];
        pmag[m] = mg; pphase[m] = p;
        float s = sinf(p);
        float c = cosf(p);
        re[m] = __fmul_rn(mg, c);
        im[m] = __fmul_rn(mg, s);
    }

    float freqf = (float)((double)f * 48000.0 / 97.0);
    float fden  = __fadd_rn(freqf, 1.0f);

    const int pa[6] = {0, 1, 2, 0, 2, 4};
    const int pb[6] = {3, 4, 5, 1, 3, 5};
    float ipdv[MM], cipd[MM], dterm[MM];
#pragma unroll
    for (int h = 0; h < MM; h++) {
        int a = pa[h], q = pb[h];
        float nimq = -im[q];
        float pr  = __fsub_rn(__fmul_rn(re[a], re[q]), __fmul_rn(im[a], nimq));
        float pim = __fadd_rn(__fmul_rn(re[a], nimq), __fmul_rn(im[a], re[q]));
        float raw = atan2f(pim, pr);
        float v   = __fdiv_rn(raw, fden);
        float r = fmodf(v, PI_F);
        if (r < 0.0f) r = __fadd_rn(r, PI_F);
        ipdv[h]  = r;
        cipd[h]  = cosf(r);
        dterm[h] = __fmul_rn(ssv[h], r);
    }
    float den = dterm[0];
    den = __fadd_rn(den, dterm[1]);
    den = __fadd_rn(den, dterm[2]);
    den = __fadd_rn(den, dterm[3]);
    den = __fadd_rn(den, dterm[4]);
    den = __fadd_rn(den, dterm[5]);

    // ---- SLOW: near-cancellation samples -> CR (double-rounded) trig ----
    if (fabsf(den) < DEN_THR) {
        float re2[MM], im2[MM];
#pragma unroll
        for (int m = 0; m < MM; m++) {
            double sd, cd;
            sincos((double)pphase[m], &sd, &cd);
            re2[m] = __fmul_rn(pmag[m], (float)cd);
            im2[m] = __fmul_rn(pmag[m], (float)sd);
        }
#pragma unroll
        for (int h = 0; h < MM; h++) {
            int a = pa[h], q = pb[h];
            float nimq = -im2[q];
            float pr  = __fsub_rn(__fmul_rn(re2[a], re2[q]), __fmul_rn(im2[a], nimq));
            float pim = __fadd_rn(__fmul_rn(re2[a], nimq), __fmul_rn(im2[a], re2[q]));
            float raw = (float)atan2((double)pim, (double)pr);  // CR f32 atan2
            float v   = __fdiv_rn(raw, fden);
            float r = fmodf(v, PI_F);                            // exact
            if (r < 0.0f) r = __fadd_rn(r, PI_F);
            ipdv[h]  = r;
            cipd[h]  = cosf(r);
            dterm[h] = __fmul_rn(ssv[h], r);
        }
        den = dterm[0];
        den = __fadd_rn(den, dterm[1]);
        den = __fadd_rn(den, dterm[2]);
        den = __fadd_rn(den, dterm[3]);
        den = __fadd_rn(den, dterm[4]);
        den = __fadd_rn(den, dterm[5]);
    }

    // ---- dpr: 36 x 6 complex MAC, packed f32x2 (well-conditioned) ----
    unsigned long long cA[MM], cB[MM];
#pragma unroll
    for (int m = 0; m < MM; m++) {
        cA[m] = pk2(re[m], im[m]);
        cB[m] = pk2(im[m], re[m]);
    }
    const ulonglong2* wp = (const ulonglong2*)sw;

    float pg[GG];
    float psum = 0.0f;
#pragma unroll
    for (int g = 0; g < GG; g++) {
        unsigned long long acc = 0ull;
#pragma unroll
        for (int m = 0; m < MM; m++) {
            ulonglong2 wv = wp[g * MM + m];
            acc = fma2(wv.x, cA[m], acc);
            acc = fma2(wv.y, cB[m], acc);
        }
        float dr, di;
        upk2(acc, dr, di);
        float pv = dr * dr + di * di;
        pg[g] = pv;
        psum += pv;
    }
    float rpsum = 1.0f / psum;

    // ---- write 48 channels, coalesced in t ----
    const int cs = FF * TT;
    float* ob = out + (b * 48) * cs + f * TT + t;
#pragma unroll
    for (int h = 0; h < MM; h++)
        ob[h * cs] = __fdiv_rn(__fmul_rn(ssv[h], ipdv[h]), den);   // af.real
#pragma unroll
    for (int g = 0; g < GG; g++)
        ob[(6 + g) * cs] = pg[g] * rpsum;                          // dpr_n
#pragma unroll
    for (int h = 0; h < MM; h++)
        ob[(42 + h) * cs] = cipd[h];                               // cos(ipd)
}

// ---------------------------------------------------------------------------
extern "C" void kernel_launch(void* const* d_in, const int* in_sizes, int n_in,
                              void* d_out, int out_size) {
    const float* big[2] = {0, 0};
    const float* angle  = 0;
    int nbig = 0;
    for (int i = 0; i < n_in; i++) {
        if (in_sizes[i] == 8 || in_sizes[i] == 32) {
            angle = (const float*)d_in[i];
        } else if (nbig < 2) {
            big[nbig++] = (const float*)d_in[i];
        }
    }
    const float* mag = big[0] ? big[0] : (const float*)d_in[0];
    const float* ph  = big[1] ? big[1] : (const float*)d_in[1];
    if (!angle) angle = (const float*)d_in[2];

    float* out = (float*)d_out;

    init_w_kernel<<<(FF * GG * MM + 255) / 256, 256>>>();
    init_sv_kernel<<<(BB * MM * FF + 255) / 256, 256>>>(angle);

    dim3 grid(BB * FF, (TT + 255) / 256);   // (776, 5)
    tasnet_fused_kernel<<<grid, 256>>>(mag, ph, out);
}

// round 17
// speedup vs baseline: 1.1696x; 1.1696x over previous
#include <cuda_runtime.h>
#include <math.h>

#define BB 8
#define MM 6
#define FF 97
#define TT 1200
#define GG 36

#define PI_F     3.14159274101257324f
#define TWOPI_F  6.28318548202514648f
#define DEN_THR  1e-3f   // libdevice tier -> f64 CR tier (calibrated: tail rel 1.84e-4)

__device__ float4 g_wpack[FF * GG * MM];
__device__ float  g_svre[BB * MM * FF];

// ---------------------------------------------------------------------------
// f32x2 packed helpers (sm_10x)
// ---------------------------------------------------------------------------
__device__ __forceinline__ unsigned long long pk2(float lo, float hi) {
    unsigned long long r;
    asm("mov.b64 %0, {%1, %2};" : "=l"(r) : "f"(lo), "f"(hi));
    return r;
}
__device__ __forceinline__ void upk2(unsigned long long v, float& lo, float& hi) {
    asm("mov.b64 {%0, %1}, %2;" : "=f"(lo), "=f"(hi) : "l"(v));
}
__device__ __forceinline__ unsigned long long fma2(unsigned long long a,
                                                   unsigned long long b,
                                                   unsigned long long c) {
    unsigned long long d;
    asm("fma.rn.f32x2 %0, %1, %2, %3;" : "=l"(d) : "l"(a), "l"(b), "l"(c));
    return d;
}

// ---------------------------------------------------------------------------
// Merged init: w (f32 trig, feeds the well-conditioned dpr_n only) +
//              Re(sv) (f64-rounded CR trig, feeds the sensitive AF chain).
// ---------------------------------------------------------------------------
__global__ void init_kernel(const float* __restrict__ angle) {
    int idx = blockIdx.x * blockDim.x + threadIdx.x;

    if (idx < FF * GG * MM) {
        int m = idx % MM;
        int g = (idx / MM) % GG;
        int f = idx / (MM * GG);
        float angm = (float)(2.0 * M_PI / 6.0) * (float)m;
        float lx = 0.05f * (cosf(angm) - 1.0f);
        float ly = 0.05f * sinf(angm);
        float grid = (float)(M_PI / 18.0) * (float)g;
        float dly = lx * cosf(grid) + ly * sinf(grid);
        float arg = (float)(-2.0 * M_PI) * (float)f * dly;
        float s, c;
        sincosf(arg, &s, &c);
        float wre = c * (1.0f / 343.0f);
        float wim = s * (1.0f / 343.0f);
        g_wpack[idx] = make_float4(wre, wre, -wim, wim);
    }

    if (idx < BB * MM * FF) {
        int f = idx % FF;
        int h = (idx / FF) % MM;
        int b = idx / (FF * MM);
        const int pa[6] = {0, 1, 2, 0, 2, 4};
        const int pb[6] = {3, 4, 5, 1, 3, 5};
        int ia = pa[h], ib = pb[h];
        double la_x = 0.05 * (cos(2.0 * M_PI * (double)ia / 6.0) - 1.0);
        double la_y = 0.05 * sin(2.0 * M_PI * (double)ia / 6.0);
        double lb_x = 0.05 * (cos(2.0 * M_PI * (double)ib / 6.0) - 1.0);
        double lb_y = 0.05 * sin(2.0 * M_PI * (double)ib / 6.0);
        float dxy0 = (float)(lb_x - la_x);
        float dxy1 = (float)(lb_y - la_y);

        float a  = angle[b];
        float ca = (float)cos((double)a);     // CR f32 cos
        float sa = (float)sin((double)a);     // CR f32 sin
        float delay = __fadd_rn(__fmul_rn(dxy0, ca), __fmul_rn(dxy1, sa));

        float freqf = (float)((double)f * 48000.0 / 97.0);
        float t1 = __fmul_rn(TWOPI_F, freqf);
        float t2 = __fmul_rn(t1, delay);
        float t3 = __fdiv_rn(t2, 343.0f);
        g_svre[idx] = (float)cos((double)t3); // CR f32 cos
    }
}

// ---------------------------------------------------------------------------
// Main fused kernel, two tiers (MUFU removed from the AF chain — its ABSOLUTE
// trig error becomes a divergent PHASE error for small magnitudes):
//  base: libdevice sincosf/atan2f, unfused f32 (delta ~1e-7 relative phase);
//        finalize if |den| >= 1e-3  ->  pole-tail rel ~1.8e-4 (calibrated).
//  CR  : |den| < 1e-3 (~0.06% samples, ~2% warps): f64-rounded bit-exact
//        chain, validated in R14.
// ---------------------------------------------------------------------------
__global__ void __launch_bounds__(256, 2)
tasnet_fused_kernel(const float* __restrict__ mag,
                    const float* __restrict__ ph,
                    float* __restrict__ out) {
    __shared__ float4 sw[GG * MM];
    __shared__ float  ssv[MM];

    int bf = blockIdx.x;
    int f = bf % FF;
    int b = bf / FF;

    for (int i = threadIdx.x; i < GG * MM; i += blockDim.x)
        sw[i] = g_wpack[f * GG * MM + i];
    if (threadIdx.x < MM)
        ssv[threadIdx.x] = g_svre[(b * MM + threadIdx.x) * FF + f];
    __syncthreads();

    int t = blockIdx.y * blockDim.x + threadIdx.x;
    if (t >= TT) return;

    const int pa[6] = {0, 1, 2, 0, 2, 4};
    const int pb[6] = {3, 4, 5, 1, 3, 5};

    // ---- base: complex spectrogram via libdevice sincosf (relative acc) ----
    const int base_in = (b * MM) * (FF * TT) + f * TT + t;
    float pphase[MM], pmag[MM];
    float re[MM], im[MM];
#pragma unroll
    for (int m = 0; m < MM; m++) {
        float mg = mag[base_in + m * (FF * TT)];
        float p  = ph [base_in + m * (FF * TT)];
        pmag[m] = mg; pphase[m] = p;
        float s, c;
        sincosf(p, &s, &c);                    // libdevice, 1-2 ulp relative
        re[m] = __fmul_rn(mg, c);
        im[m] = __fmul_rn(mg, s);
    }

    float freqf = (float)((double)f * 48000.0 / 97.0);
    float fden  = __fadd_rn(freqf, 1.0f);

    float afv[MM], cipd[MM], dterm[MM];
#pragma unroll
    for (int h = 0; h < MM; h++) {
        int a = pa[h], q = pb[h];
        float nimq = -im[q];
        float pr  = __fsub_rn(__fmul_rn(re[a], re[q]), __fmul_rn(im[a], nimq));
        float pim = __fadd_rn(__fmul_rn(re[a], nimq), __fmul_rn(im[a], re[q]));
        float raw = atan2f(pim, pr);           // |raw| <= pi
        float v   = __fdiv_rn(raw, fden);      // |v| <= pi
        float r = v;                            // mod(v, pi): exact for |v|<=pi
        if (r < 0.0f)       r = __fadd_rn(r, PI_F);
        else if (r >= PI_F) r = __fsub_rn(r, PI_F);
        afv[h]   = r;                           // holds ipd for now
        cipd[h]  = __cosf(r);                   // r in [0,pi): no reduction
        dterm[h] = __fmul_rn(ssv[h], r);
    }
    float den = dterm[0];
    den = __fadd_rn(den, dterm[1]);
    den = __fadd_rn(den, dterm[2]);
    den = __fadd_rn(den, dterm[3]);
    den = __fadd_rn(den, dterm[4]);
    den = __fadd_rn(den, dterm[5]);

    if (fabsf(den) >= DEN_THR) {
        // finalize af with fast division (rel 2e-7: negligible vs budget)
#pragma unroll
        for (int h = 0; h < MM; h++)
            afv[h] = __fdividef(ssv[h] * afv[h], den);
    } else {
        // ---- CR tier: bit-exact chain (f64-rounded trig), R14-validated ----
        float re2[MM], im2[MM];
#pragma unroll
        for (int m = 0; m < MM; m++) {
            double sd, cd;
            sincos((double)pphase[m], &sd, &cd);
            re2[m] = __fmul_rn(pmag[m], (float)cd);
            im2[m] = __fmul_rn(pmag[m], (float)sd);
        }
        float ipdv[MM];
#pragma unroll
        for (int h = 0; h < MM; h++) {
            int a = pa[h], q = pb[h];
            float nimq = -im2[q];
            float pr  = __fsub_rn(__fmul_rn(re2[a], re2[q]), __fmul_rn(im2[a], nimq));
            float pim = __fadd_rn(__fmul_rn(re2[a], nimq), __fmul_rn(im2[a], re2[q]));
            float raw = (float)atan2((double)pim, (double)pr);  // CR f32 atan2
            float v   = __fdiv_rn(raw, fden);
            float r = fmodf(v, PI_F);
            if (r < 0.0f) r = __fadd_rn(r, PI_F);
            ipdv[h]  = r;
            cipd[h]  = cosf(r);
            dterm[h] = __fmul_rn(ssv[h], r);
        }
        den = dterm[0];
        den = __fadd_rn(den, dterm[1]);
        den = __fadd_rn(den, dterm[2]);
        den = __fadd_rn(den, dterm[3]);
        den = __fadd_rn(den, dterm[4]);
        den = __fadd_rn(den, dterm[5]);
#pragma unroll
        for (int h = 0; h < MM; h++)
            afv[h] = __fdiv_rn(__fmul_rn(ssv[h], ipdv[h]), den);
    }

    // ---- dpr: 36 x 6 complex MAC, packed f32x2 (uses base-tier re/im;
    //      absolute-error analysis: contribution < 1e-3 of budget) ----
    unsigned long long cA[MM], cB[MM];
#pragma unroll
    for (int m = 0; m < MM; m++) {
        cA[m] = pk2(re[m], im[m]);
        cB[m] = pk2(im[m], re[m]);
    }
    const ulonglong2* wp = (const ulonglong2*)sw;

    float pg[GG];
    float psum = 0.0f;
#pragma unroll
    for (int g = 0; g < GG; g++) {
        unsigned long long acc = 0ull;
#pragma unroll
        for (int m = 0; m < MM; m++) {
            ulonglong2 wv = wp[g * MM + m];
            acc = fma2(wv.x, cA[m], acc);
            acc = fma2(wv.y, cB[m], acc);
        }
        float dr, di;
        upk2(acc, dr, di);
        float pv = dr * dr + di * di;
        pg[g] = pv;
        psum += pv;
    }
    float rpsum = __fdividef(1.0f, psum);

    // ---- write 48 channels, coalesced in t ----
    const int cs = FF * TT;
    float* ob = out + (b * 48) * cs + f * TT + t;
#pragma unroll
    for (int h = 0; h < MM; h++)
        ob[h * cs] = afv[h];                      // af.real
#pragma unroll
    for (int g = 0; g < GG; g++)
        ob[(6 + g) * cs] = pg[g] * rpsum;         // dpr_n
#pragma unroll
    for (int h = 0; h < MM; h++)
        ob[(42 + h) * cs] = cipd[h];              // cos(ipd)
}

// ---------------------------------------------------------------------------
extern "C" void kernel_launch(void* const* d_in, const int* in_sizes, int n_in,
                              void* d_out, int out_size) {
    const float* big[2] = {0, 0};
    const float* angle  = 0;
    int nbig = 0;
    for (int i = 0; i < n_in; i++) {
        if (in_sizes[i] == 8 || in_sizes[i] == 32) {
            angle = (const float*)d_in[i];
        } else if (nbig < 2) {
            big[nbig++] = (const float*)d_in[i];
        }
    }
    const float* mag = big[0] ? big[0] : (const float*)d_in[0];
    const float* ph  = big[1] ? big[1] : (const float*)d_in[1];
    if (!angle) angle = (const float*)d_in[2];

    float* out = (float*)d_out;

    init_kernel<<<(FF * GG * MM + 255) / 256, 256>>>(angle);

    dim3 grid(BB * FF, (TT + 255) / 256);   // (776, 5)
    tasnet_fused_kernel<<<grid, 256>>>(mag, ph, out);
}